// round 6
// baseline (speedup 1.0000x reference)
#include <cuda_runtime.h>
#include <cuda_bf16.h>
#include <cstdint>

// Problem constants (fixed by the dataset shapes)
#define BB   16
#define KK   64
#define HH   160
#define WW   160
#define HWC  (HH * WW)          // 25600
#define NQ   (WW / 4)           // 40 x-quads per row
#define NGRP 8                  // k-groups per block (= threadIdx.x)
#define KPT  (KK / NGRP)        // 8 keypoints per thread
#define NTHR (NQ * NGRP)        // 320 threads
#define EPS_F 1e-5f

__device__ __forceinline__ float ex2_approx(float x) {
    float r;
    asm("ex2.approx.ftz.f32 %0, %1;" : "=f"(r) : "f"(x));
    return r;
}
__device__ __forceinline__ float rcp_approx(float x) {
    float r;
    asm("rcp.approx.ftz.f32 %0, %1;" : "=f"(r) : "f"(x));
    return r;
}
// Packed 2xfp32 ops (sm_100+); operands live in 64-bit register pairs.
__device__ __forceinline__ uint64_t fma2(uint64_t a, uint64_t b, uint64_t c) {
    uint64_t d;
    asm("fma.rn.f32x2 %0, %1, %2, %3;" : "=l"(d) : "l"(a), "l"(b), "l"(c));
    return d;
}
__device__ __forceinline__ uint64_t add2(uint64_t a, uint64_t b) {
    uint64_t d;
    asm("add.rn.f32x2 %0, %1, %2;" : "=l"(d) : "l"(a), "l"(b));
    return d;
}
__device__ __forceinline__ uint64_t mul2(uint64_t a, uint64_t b) {
    uint64_t d;
    asm("mul.rn.f32x2 %0, %1, %2;" : "=l"(d) : "l"(a), "l"(b));
    return d;
}
__device__ __forceinline__ uint64_t pack2(float lo, float hi) {
    uint64_t d;
    asm("mov.b64 %0, {%1, %2};" : "=l"(d) : "f"(lo), "f"(hi));
    return d;
}
__device__ __forceinline__ void unpack2(uint64_t v, float& lo, float& hi) {
    asm("mov.b64 {%0, %1}, %2;" : "=f"(lo), "=f"(hi) : "l"(v));
}

__global__ __launch_bounds__(NTHR)
void recon_conf_map_kernel(const float* __restrict__ kp,    // [B,K,2] (x,y)
                           const float* __restrict__ psx,   // scalar
                           const float* __restrict__ psy,   // scalar
                           const float* __restrict__ prho,  // scalar
                           float* __restrict__ out)         // [B,K,H,W]
{
    // Per-(k,row) coeffs pre-packed as (q0, q0, q1, q1): e(fx) = Bq*fx^2 + q1*fx + q0
    __shared__ float4 sq[KK];

    const int b  = blockIdx.x / HH;
    const int y  = blockIdx.x % HH;
    const int g  = threadIdx.x;          // 0..7   k-group
    const int qx = threadIdx.y;          // 0..39  x-quad
    const int tid = g + NGRP * qx;

    // Scalars (broadcast LDG, L1-cached)
    const float sx  = psx[0];
    const float sy  = psy[0];
    const float rho = prho[0];

    const float omr2 = 1.0f - rho * rho;
    const float num1 = -0.5f / omr2;
    const float L2E  = 1.4426950408889634f;           // log2(e)
    const float den  = 1.0f / (6.2831853071795864f * sx * sy * sqrtf(omr2));
    const float l2den = log2f(den);

    // base-2 exponent = A*dy^2 + Bq*dx^2 + C*dy*dx (+ l2den)
    const float A  = num1 * L2E / (sy * sy);
    const float Bq = num1 * L2E / (sx * sx);
    const float C  = num1 * L2E * (-2.0f * rho) / (sx * sy);

    // Per-k 1-D quadratic in fx for this row:
    //   e = Bq*fx^2 + (C*dy - 2*Bq*kx)*fx + [A*dy^2 + Bq*kx^2 - (C*dy)*kx + l2den]
    if (tid < KK) {
        float2 p = reinterpret_cast<const float2*>(kp)[b * KK + tid];
        const float kx = p.x;
        const float dy = (float)y - p.y;
        const float cy = C * dy;
        const float ay = fmaf(A * dy, dy, l2den);
        const float q1 = fmaf(-2.0f * Bq, kx, cy);
        const float q0 = fmaf(kx, fmaf(Bq, kx, -cy), ay);
        sq[tid] = make_float4(q0, q0, q1, q1);
    }
    __syncthreads();

    const float fx0 = (float)(4 * qx);
    const uint64_t x01 = pack2(fx0,        fx0 + 1.0f);
    const uint64_t x23 = pack2(fx0 + 2.0f, fx0 + 3.0f);
    // bf = Bq*fx^2 per lane
    const uint64_t bf01 = pack2(Bq * fx0 * fx0,
                                Bq * (fx0 + 1.0f) * (fx0 + 1.0f));
    const uint64_t bf23 = pack2(Bq * (fx0 + 2.0f) * (fx0 + 2.0f),
                                Bq * (fx0 + 3.0f) * (fx0 + 3.0f));
    const int kbase = g * KPT;

    uint64_t v01[KPT], v23[KPT];
    uint64_t s01 = 0, s23 = 0;   // 0x0 == packed (+0.f, +0.f)

#pragma unroll
    for (int k = 0; k < KPT; ++k) {
        const float4 q = sq[kbase + k];          // (q0,q0,q1,q1) via LDS.128
        uint64_t q0p, q1p;
        asm("mov.b64 %0, {%2, %3}; mov.b64 %1, {%4, %5};"
            : "=l"(q0p), "=l"(q1p) : "f"(q.x), "f"(q.y), "f"(q.z), "f"(q.w));
        const uint64_t e01 = add2(fma2(q1p, x01, bf01), q0p);
        const uint64_t e23 = add2(fma2(q1p, x23, bf23), q0p);
        float a0, a1, a2, a3;
        unpack2(e01, a0, a1);
        unpack2(e23, a2, a3);
        const uint64_t w01 = pack2(ex2_approx(a0), ex2_approx(a1));
        const uint64_t w23 = pack2(ex2_approx(a2), ex2_approx(a3));
        v01[k] = w01;
        v23[k] = w23;
        s01 = add2(s01, w01);
        s23 = add2(s23, w23);
    }

    // Butterfly-reduce the per-x sums over the 8 k-group lanes (lanes differ in
    // the low 3 bits only: lane = g + 8*(qx%4)).
    float sa, sb, sc, sd;
    unpack2(s01, sa, sb);
    unpack2(s23, sc, sd);
#pragma unroll
    for (int m = 1; m < NGRP; m <<= 1) {
        sa += __shfl_xor_sync(0xffffffffu, sa, m);
        sb += __shfl_xor_sync(0xffffffffu, sb, m);
        sc += __shfl_xor_sync(0xffffffffu, sc, m);
        sd += __shfl_xor_sync(0xffffffffu, sd, m);
    }
    const uint64_t inv01 = pack2(rcp_approx(sa + EPS_F), rcp_approx(sb + EPS_F));
    const uint64_t inv23 = pack2(rcp_approx(sc + EPS_F), rcp_approx(sd + EPS_F));

    // out[b, kbase+k, y, 4*qx..4*qx+3] — one STG.128 per k
    float* __restrict__ obase = out + ((size_t)b * KK + kbase) * HWC
                                    + (size_t)y * WW + 4 * qx;
#pragma unroll
    for (int k = 0; k < KPT; ++k) {
        const uint64_t r01 = mul2(v01[k], inv01);
        const uint64_t r23 = mul2(v23[k], inv23);
        float4 r;
        unpack2(r01, r.x, r.y);
        unpack2(r23, r.z, r.w);
        *reinterpret_cast<float4*>(obase + (size_t)k * HWC) = r;
    }
}

extern "C" void kernel_launch(void* const* d_in, const int* in_sizes, int n_in,
                              void* d_out, int out_size) {
    // metadata order: keypoints, std_x, std_y, correlation, DetectionMap (unused)
    const float* kp   = (const float*)d_in[0];
    const float* psx  = (const float*)d_in[1];
    const float* psy  = (const float*)d_in[2];
    const float* prho = (const float*)d_in[3];
    float* out = (float*)d_out;

    dim3 block(NGRP, NQ);                 // 320 threads: (k-group, x-quad)
    const int grid = BB * HH;             // 2560 blocks, one per (batch,row)
    recon_conf_map_kernel<<<grid, block>>>(kp, psx, psy, prho, out);
}

// round 7
// speedup vs baseline: 1.9889x; 1.9889x over previous
#include <cuda_runtime.h>
#include <cuda_bf16.h>
#include <cstdint>

// Problem constants (fixed by the dataset shapes)
#define BB   16
#define KK   64
#define HH   160
#define WW   160
#define HWC  (HH * WW)            // 25600
#define NROWS (BB * HH)           // 2560
#define SPANS 5                   // 32-pixel spans per row
#define NWARPS (NROWS * SPANS)    // 12800 independent warps
#define KPT  16                   // keypoints per thread (4 g-groups)
#define EPS_F 1e-5f

// Precomputed per-(b,y,k) 1-D quadratic coefficients: e(fx) = Bq*fx^2 + q1*fx + q0
__device__ float2 g_cf[NROWS * KK];   // 1.31 MB, lives in L2

__device__ __forceinline__ float ex2_approx(float x) {
    float r;
    asm("ex2.approx.ftz.f32 %0, %1;" : "=f"(r) : "f"(x));
    return r;
}
__device__ __forceinline__ float rcp_approx(float x) {
    float r;
    asm("rcp.approx.ftz.f32 %0, %1;" : "=f"(r) : "f"(x));
    return r;
}

// ---------------- kernel 1: coefficient table ----------------
__global__ __launch_bounds__(256)
void coeff_kernel(const float* __restrict__ kp,
                  const float* __restrict__ psx,
                  const float* __restrict__ psy,
                  const float* __restrict__ prho)
{
    const int idx = blockIdx.x * 256 + threadIdx.x;   // (b,y,k) flat
    if (idx >= NROWS * KK) return;
    const int k   = idx & (KK - 1);
    const int row = idx >> 6;           // b*HH + y
    const int b   = row / HH;
    const int y   = row - b * HH;

    const float sx  = psx[0];
    const float sy  = psy[0];
    const float rho = prho[0];

    const float omr2 = 1.0f - rho * rho;
    const float num1 = -0.5f / omr2;
    const float L2E  = 1.4426950408889634f;
    const float den  = 1.0f / (6.2831853071795864f * sx * sy * sqrtf(omr2));
    const float l2den = log2f(den);

    const float A  = num1 * L2E / (sy * sy);
    const float Bq = num1 * L2E / (sx * sx);
    const float C  = num1 * L2E * (-2.0f * rho) / (sx * sy);

    const float2 p = reinterpret_cast<const float2*>(kp)[b * KK + k];
    const float kx = p.x;
    const float dy = (float)y - p.y;
    const float cy = C * dy;
    const float ay = fmaf(A * dy, dy, l2den);
    const float q1 = fmaf(-2.0f * Bq, kx, cy);
    const float q0 = fmaf(kx, fmaf(Bq, kx, -cy), ay);
    g_cf[idx] = make_float2(q0, q1);
}

// ---------------- kernel 2: main (barrier-free, warp-autonomous) ----------------
#define NTHR2 256
__global__ __launch_bounds__(NTHR2)
void recon_conf_map_kernel(const float* __restrict__ psx,
                           const float* __restrict__ prho,
                           float* __restrict__ out)     // [B,K,H,W]
{
    const int t    = blockIdx.x * NTHR2 + threadIdx.x;
    const int w    = t >> 5;                 // global warp id
    const int lane = t & 31;
    const int row  = w / SPANS;              // b*HH + y
    const int span = w - row * SPANS;
    const int b    = row / HH;
    const int y    = row - b * HH;

    const int qx = lane & 7;                 // 0..7: x-quad within span
    const int g  = lane >> 3;                // 0..3: k-group
    const int kbase = g * KPT;

    // Bq only (everything else folded into the table)
    const float sx  = psx[0];
    const float rho = prho[0];
    const float omr2 = 1.0f - rho * rho;
    const float Bq = (-0.5f * 1.4426950408889634f) / (omr2 * sx * sx);

    const float fx0 = (float)(span * 32 + qx * 4);
    const float f0 = fx0, f1 = fx0 + 1.0f, f2 = fx0 + 2.0f, f3 = fx0 + 3.0f;
    const float p0 = Bq * f0 * f0, p1 = Bq * f1 * f1;
    const float p2 = Bq * f2 * f2, p3 = Bq * f3 * f3;

    // Coefficients for this thread's 16 k: 8 x float4 (2 k each), broadcast LDG
    const float4* __restrict__ cfp =
        reinterpret_cast<const float4*>(g_cf + row * KK + kbase);

    float4 vals[KPT];
    float s0 = 0.f, s1 = 0.f, s2 = 0.f, s3 = 0.f;

#pragma unroll
    for (int j = 0; j < KPT / 2; ++j) {
        const float4 c = cfp[j];             // (q0a, q1a, q0b, q1b)
        {
            float4 v;
            v.x = ex2_approx(fmaf(c.y, f0, p0) + c.x);
            v.y = ex2_approx(fmaf(c.y, f1, p1) + c.x);
            v.z = ex2_approx(fmaf(c.y, f2, p2) + c.x);
            v.w = ex2_approx(fmaf(c.y, f3, p3) + c.x);
            vals[2 * j] = v;
            s0 += v.x; s1 += v.y; s2 += v.z; s3 += v.w;
        }
        {
            float4 v;
            v.x = ex2_approx(fmaf(c.w, f0, p0) + c.z);
            v.y = ex2_approx(fmaf(c.w, f1, p1) + c.z);
            v.z = ex2_approx(fmaf(c.w, f2, p2) + c.z);
            v.w = ex2_approx(fmaf(c.w, f3, p3) + c.z);
            vals[2 * j + 1] = v;
            s0 += v.x; s1 += v.y; s2 += v.z; s3 += v.w;
        }
    }

    // Sum over all 64 k = butterfly over the 4 g-groups (lane bits 3,4)
#pragma unroll
    for (int m = 8; m < 32; m <<= 1) {
        s0 += __shfl_xor_sync(0xffffffffu, s0, m);
        s1 += __shfl_xor_sync(0xffffffffu, s1, m);
        s2 += __shfl_xor_sync(0xffffffffu, s2, m);
        s3 += __shfl_xor_sync(0xffffffffu, s3, m);
    }
    const float i0 = rcp_approx(s0 + EPS_F);
    const float i1 = rcp_approx(s1 + EPS_F);
    const float i2 = rcp_approx(s2 + EPS_F);
    const float i3 = rcp_approx(s3 + EPS_F);

    // Stores: per STG.128 warp-op = 4 k-planes x 128B aligned segments (16 full sectors)
    float4* __restrict__ o = reinterpret_cast<float4*>(
        out + ((size_t)b * KK + kbase) * HWC + (size_t)y * WW) + (span * 8 + qx);
#pragma unroll
    for (int k = 0; k < KPT; ++k) {
        const float4 v = vals[k];
        o[(size_t)k * (HWC / 4)] =
            make_float4(v.x * i0, v.y * i1, v.z * i2, v.w * i3);
    }
}

extern "C" void kernel_launch(void* const* d_in, const int* in_sizes, int n_in,
                              void* d_out, int out_size) {
    // metadata order: keypoints, std_x, std_y, correlation, DetectionMap (unused)
    const float* kp   = (const float*)d_in[0];
    const float* psx  = (const float*)d_in[1];
    const float* psy  = (const float*)d_in[2];
    const float* prho = (const float*)d_in[3];
    float* out = (float*)d_out;

    coeff_kernel<<<(NROWS * KK + 255) / 256, 256>>>(kp, psx, psy, prho);

    const int total_threads = NWARPS * 32;            // 409600
    recon_conf_map_kernel<<<total_threads / NTHR2, NTHR2>>>(psx, prho, out);
}

// round 8
// speedup vs baseline: 2.2215x; 1.1169x over previous
#include <cuda_runtime.h>
#include <cuda_bf16.h>
#include <cstdint>

// Problem constants (fixed by the dataset shapes)
#define BB   16
#define KK   64
#define HH   160
#define WW   160
#define HWC  (HH * WW)            // 25600
#define NROWS (BB * HH)           // 2560
#define SPANS 10                  // 16-pixel spans per row (warp covers 16 px)
#define NWARPS (NROWS * SPANS)    // 25600 independent warps
#define KPT  8                    // keypoints per thread (8 g-groups)
#define NTHR 256
#define EPS_F 1e-5f

__device__ __forceinline__ float ex2_approx(float x) {
    float r;
    asm("ex2.approx.ftz.f32 %0, %1;" : "=f"(r) : "f"(x));
    return r;
}
__device__ __forceinline__ float rcp_approx(float x) {
    float r;
    asm("rcp.approx.ftz.f32 %0, %1;" : "=f"(r) : "f"(x));
    return r;
}

// Single kernel: warp-autonomous, no barriers, no shared memory.
// Warp = 16 consecutive pixels of one row; lane = (qx 0..3, g 0..7);
// thread owns 4 px x 8 k; coefficients computed on the fly from keypoints.
__global__ __launch_bounds__(NTHR, 4)
void recon_conf_map_kernel(const float* __restrict__ kp,    // [B,K,2]
                           const float* __restrict__ psx,
                           const float* __restrict__ psy,
                           const float* __restrict__ prho,
                           float* __restrict__ out)         // [B,K,H,W]
{
    const int t    = blockIdx.x * NTHR + threadIdx.x;
    const int w    = t >> 5;                 // global warp id
    const int lane = t & 31;
    const int row  = w / SPANS;              // b*HH + y
    const int span = w - row * SPANS;
    const int b    = row / HH;
    const int y    = row - b * HH;

    const int qx = lane & 3;                 // 0..3: x-quad within 16-px span
    const int g  = lane >> 2;                // 0..7: k-group
    const int kbase = g * KPT;

    // Scalars (broadcast LDG, L1-cached)
    const float sx  = psx[0];
    const float sy  = psy[0];
    const float rho = prho[0];

    const float omr2 = 1.0f - rho * rho;
    const float num1 = -0.5f / omr2;
    const float L2E  = 1.4426950408889634f;
    const float den  = 1.0f / (6.2831853071795864f * sx * sy * sqrtf(omr2));
    const float l2den = log2f(den);

    // base-2 exponent = A*dy^2 + Bq*dx^2 + C*dy*dx (+ l2den)
    const float A  = num1 * L2E / (sy * sy);
    const float Bq = num1 * L2E / (sx * sx);
    const float C  = num1 * L2E * (-2.0f * rho) / (sx * sy);
    const float nBq2 = -2.0f * Bq;

    const float fx0 = (float)(span * 16 + qx * 4);
    const float f0 = fx0, f1 = fx0 + 1.0f, f2 = fx0 + 2.0f, f3 = fx0 + 3.0f;
    const float p0 = Bq * f0 * f0, p1 = Bq * f1 * f1;
    const float p2 = Bq * f2 * f2, p3 = Bq * f3 * f3;

    const float2* __restrict__ kpp =
        reinterpret_cast<const float2*>(kp) + b * KK + kbase;
    const float fy = (float)y;

    float4 vals[KPT];
    float s0 = 0.f, s1 = 0.f, s2 = 0.f, s3 = 0.f;

#pragma unroll
    for (int k = 0; k < KPT; ++k) {
        // Per-k 1-D quadratic in fx for this row (computed on the fly):
        //   e = Bq*fx^2 + (C*dy - 2*Bq*kx)*fx + [A*dy^2 + Bq*kx^2 - (C*dy)*kx + l2den]
        const float2 p  = kpp[k];            // broadcast within g-group, L1-hit
        const float kx = p.x;
        const float dy = fy - p.y;
        const float cy = C * dy;
        const float ay = fmaf(A * dy, dy, l2den);
        const float q1 = fmaf(nBq2, kx, cy);
        const float q0 = fmaf(kx, fmaf(Bq, kx, -cy), ay);

        float4 v;
        v.x = ex2_approx(fmaf(q1, f0, p0) + q0);
        v.y = ex2_approx(fmaf(q1, f1, p1) + q0);
        v.z = ex2_approx(fmaf(q1, f2, p2) + q0);
        v.w = ex2_approx(fmaf(q1, f3, p3) + q0);
        vals[k] = v;
        s0 += v.x; s1 += v.y; s2 += v.z; s3 += v.w;
    }

    // Sum over all 64 k = butterfly over the 8 g-groups (lane bits 2..4)
#pragma unroll
    for (int m = 4; m < 32; m <<= 1) {
        s0 += __shfl_xor_sync(0xffffffffu, s0, m);
        s1 += __shfl_xor_sync(0xffffffffu, s1, m);
        s2 += __shfl_xor_sync(0xffffffffu, s2, m);
        s3 += __shfl_xor_sync(0xffffffffu, s3, m);
    }
    const float i0 = rcp_approx(s0 + EPS_F);
    const float i1 = rcp_approx(s1 + EPS_F);
    const float i2 = rcp_approx(s2 + EPS_F);
    const float i3 = rcp_approx(s3 + EPS_F);

    // Stores: per STG.128 warp-op, each of 8 k-planes gets a 64B-aligned
    // contiguous 64B segment (2 full sectors) — no wasted sectors.
    float4* __restrict__ o = reinterpret_cast<float4*>(
        out + ((size_t)b * KK + kbase) * HWC + (size_t)y * WW) + (span * 4 + qx);
#pragma unroll
    for (int k = 0; k < KPT; ++k) {
        const float4 v = vals[k];
        o[(size_t)k * (HWC / 4)] =
            make_float4(v.x * i0, v.y * i1, v.z * i2, v.w * i3);
    }
}

extern "C" void kernel_launch(void* const* d_in, const int* in_sizes, int n_in,
                              void* d_out, int out_size) {
    // metadata order: keypoints, std_x, std_y, correlation, DetectionMap (unused)
    const float* kp   = (const float*)d_in[0];
    const float* psx  = (const float*)d_in[1];
    const float* psy  = (const float*)d_in[2];
    const float* prho = (const float*)d_in[3];
    float* out = (float*)d_out;

    const int total_threads = NWARPS * 32;            // 819200
    recon_conf_map_kernel<<<total_threads / NTHR, NTHR>>>(kp, psx, psy, prho, out);
}

// round 10
// speedup vs baseline: 2.2843x; 1.0283x over previous
#include <cuda_runtime.h>
#include <cuda_bf16.h>
#include <cstdint>

// Problem constants (fixed by the dataset shapes)
#define BB   16
#define KK   64
#define HH   160
#define WW   160
#define HWC  (HH * WW)            // 25600
#define NROWS (BB * HH)           // 2560
#define SPANS 10                  // 16-pixel spans per row (warp covers 16 px)
#define NWARPS (NROWS * SPANS)    // 25600 independent warps
#define KPT  8                    // keypoints per thread (8 g-groups)
#define NPAIR (KPT / 2)           // processed as 4 k-pairs (f32x2 packed)
#define NTHR 256
#define EPS_F 1e-5f

__device__ __forceinline__ float ex2_approx(float x) {
    float r; asm("ex2.approx.ftz.f32 %0, %1;" : "=f"(r) : "f"(x)); return r;
}
__device__ __forceinline__ float rcp_approx(float x) {
    float r; asm("rcp.approx.ftz.f32 %0, %1;" : "=f"(r) : "f"(x)); return r;
}
// Packed 2xfp32 (sm_100+): operands in 64-bit register pairs.
__device__ __forceinline__ uint64_t fma2(uint64_t a, uint64_t b, uint64_t c) {
    uint64_t d; asm("fma.rn.f32x2 %0, %1, %2, %3;" : "=l"(d) : "l"(a), "l"(b), "l"(c)); return d;
}
__device__ __forceinline__ uint64_t add2(uint64_t a, uint64_t b) {
    uint64_t d; asm("add.rn.f32x2 %0, %1, %2;" : "=l"(d) : "l"(a), "l"(b)); return d;
}
__device__ __forceinline__ uint64_t mul2(uint64_t a, uint64_t b) {
    uint64_t d; asm("mul.rn.f32x2 %0, %1, %2;" : "=l"(d) : "l"(a), "l"(b)); return d;
}
__device__ __forceinline__ uint64_t pack2(float lo, float hi) {
    uint64_t d; asm("mov.b64 %0, {%1, %2};" : "=l"(d) : "f"(lo), "f"(hi)); return d;
}
__device__ __forceinline__ void unpack2(uint64_t v, float& lo, float& hi) {
    asm("mov.b64 {%0, %1}, %2;" : "=f"(lo), "=f"(hi) : "l"(v));
}

// Warp-autonomous, no barriers/smem. Warp = 16 consecutive px of one row;
// lane = (qx 0..3, g 0..7); thread = 4 px x 8 k (4 packed k-pairs).
// Along x the Gaussian obeys v(x+1)=v(x)*t(x), t(x+1)=t(x)*u: 2 EX2 per k
// instead of 4, rest is f32x2 packed math.
__global__ __launch_bounds__(NTHR, 4)
void recon_conf_map_kernel(const float* __restrict__ kp,    // [B,K,2]
                           const float* __restrict__ psx,
                           const float* __restrict__ psy,
                           const float* __restrict__ prho,
                           float* __restrict__ out)         // [B,K,H,W]
{
    const int t    = blockIdx.x * NTHR + threadIdx.x;
    const int w    = t >> 5;
    const int lane = t & 31;
    const int row  = w / SPANS;              // b*HH + y
    const int span = w - row * SPANS;
    const int b    = row / HH;
    const int y    = row - b * HH;

    const int qx = lane & 3;                 // x-quad within 16-px span
    const int g  = lane >> 2;                // k-group
    const int kbase = g * KPT;

    // Scalars
    const float sx  = psx[0];
    const float sy  = psy[0];
    const float rho = prho[0];

    const float omr2 = 1.0f - rho * rho;
    const float num1 = -0.5f / omr2;
    const float L2E  = 1.4426950408889634f;
    const float den  = 1.0f / (6.2831853071795864f * sx * sy * sqrtf(omr2));
    const float l2den = log2f(den);

    // base-2 exponent e(x) = Bq*x^2 + q1*x + q0 per (k,row)
    const float A  = num1 * L2E / (sy * sy);
    const float Bq = num1 * L2E / (sx * sx);
    const float C  = num1 * L2E * (-2.0f * rho) / (sx * sy);

    const float fx0 = (float)(span * 16 + qx * 4);
    const float fy  = (float)y;

    // Packed broadcast constants
    const uint64_t Ap    = pack2(A, A);
    const uint64_t Bqp   = pack2(Bq, Bq);
    const uint64_t Cp    = pack2(C, C);
    const uint64_t Cnp   = pack2(-C, -C);
    const uint64_t nBq2p = pack2(-2.0f * Bq, -2.0f * Bq);
    const uint64_t l2dp  = pack2(l2den, l2den);
    const uint64_t fyp   = pack2(fy, fy);
    const uint64_t neg1p = pack2(-1.0f, -1.0f);
    const uint64_t f0p   = pack2(fx0, fx0);
    const uint64_t p0p   = pack2(Bq * fx0 * fx0, Bq * fx0 * fx0);
    const float    rb    = Bq * (2.0f * fx0 + 1.0f);   // ratio exponent base at x=fx0
    const uint64_t rbp   = pack2(rb, rb);
    const float    u     = ex2_approx(2.0f * Bq);      // per-step ratio of ratios
    const uint64_t up    = pack2(u, u);

    // keypoints for this thread's 8 k: 4 float4 loads (kx_a, ky_a, kx_b, ky_b)
    const float4* __restrict__ kpp4 =
        reinterpret_cast<const float4*>(kp + 2 * (b * KK + kbase));

    uint64_t vs[NPAIR][4];
    uint64_t acc0 = 0, acc1 = 0, acc2 = 0, acc3 = 0;  // packed (+0,+0)

#pragma unroll
    for (int j = 0; j < NPAIR; ++j) {
        const float4 kk = kpp4[j];
        const uint64_t kxp = pack2(kk.x, kk.z);
        const uint64_t kyp = pack2(kk.y, kk.w);
        // coefficients (packed over the k-pair):
        //   dy = fy - ky; cy = C*dy; ay = A*dy^2 + l2den
        //   q1 = -2Bq*kx + cy;  q0 = kx*(Bq*kx - cy) + ay
        const uint64_t dyp  = fma2(kyp, neg1p, fyp);
        const uint64_t cyp  = mul2(Cp,  dyp);
        const uint64_t cynp = mul2(Cnp, dyp);
        const uint64_t ayp  = fma2(mul2(Ap, dyp), dyp, l2dp);
        const uint64_t q1p  = fma2(nBq2p, kxp, cyp);
        const uint64_t q0p  = fma2(kxp, fma2(Bqp, kxp, cynp), ayp);

        // seed value and ratio at x = fx0
        const uint64_t e0p  = add2(fma2(q1p, f0p, p0p), q0p);
        const uint64_t t0ep = add2(q1p, rbp);
        float ea, eb, ta, tb;
        unpack2(e0p,  ea, eb);
        unpack2(t0ep, ta, tb);
        const uint64_t v0p = pack2(ex2_approx(ea), ex2_approx(eb));
        const uint64_t t0p = pack2(ex2_approx(ta), ex2_approx(tb));

        // geometric chain across the 4 pixels
        const uint64_t v1p = mul2(v0p, t0p);
        const uint64_t t1p = mul2(t0p, up);
        const uint64_t v2p = mul2(v1p, t1p);
        const uint64_t t2p = mul2(t1p, up);
        const uint64_t v3p = mul2(v2p, t2p);

        vs[j][0] = v0p; vs[j][1] = v1p; vs[j][2] = v2p; vs[j][3] = v3p;
        acc0 = add2(acc0, v0p);
        acc1 = add2(acc1, v1p);
        acc2 = add2(acc2, v2p);
        acc3 = add2(acc3, v3p);
    }

    // collapse packed halves, then butterfly over the 8 g-groups (lane bits 2..4)
    float s0, s1, s2, s3, hx;
    unpack2(acc0, s0, hx); s0 += hx;
    unpack2(acc1, s1, hx); s1 += hx;
    unpack2(acc2, s2, hx); s2 += hx;
    unpack2(acc3, s3, hx); s3 += hx;
#pragma unroll
    for (int m = 4; m < 32; m <<= 1) {
        s0 += __shfl_xor_sync(0xffffffffu, s0, m);
        s1 += __shfl_xor_sync(0xffffffffu, s1, m);
        s2 += __shfl_xor_sync(0xffffffffu, s2, m);
        s3 += __shfl_xor_sync(0xffffffffu, s3, m);
    }
    const float i0 = rcp_approx(s0 + EPS_F);
    const float i1 = rcp_approx(s1 + EPS_F);
    const float i2 = rcp_approx(s2 + EPS_F);
    const float i3 = rcp_approx(s3 + EPS_F);
    const uint64_t i0p = pack2(i0, i0);
    const uint64_t i1p = pack2(i1, i1);
    const uint64_t i2p = pack2(i2, i2);
    const uint64_t i3p = pack2(i3, i3);

    // Stores: per STG.128 warp-op each of 8 k-planes gets a contiguous,
    // 64B-aligned 64B segment (2 full sectors) — no wasted sectors.
    float4* __restrict__ o = reinterpret_cast<float4*>(
        out + ((size_t)b * KK + kbase) * HWC + (size_t)y * WW) + (span * 4 + qx);
#pragma unroll
    for (int j = 0; j < NPAIR; ++j) {
        const uint64_t r0 = mul2(vs[j][0], i0p);
        const uint64_t r1 = mul2(vs[j][1], i1p);
        const uint64_t r2 = mul2(vs[j][2], i2p);
        const uint64_t r3 = mul2(vs[j][3], i3p);
        float4 va, vb;                        // lo/hi halves are free reg names
        unpack2(r0, va.x, vb.x);
        unpack2(r1, va.y, vb.y);
        unpack2(r2, va.z, vb.z);
        unpack2(r3, va.w, vb.w);
        o[(size_t)(2 * j)     * (HWC / 4)] = va;
        o[(size_t)(2 * j + 1) * (HWC / 4)] = vb;
    }
}

extern "C" void kernel_launch(void* const* d_in, const int* in_sizes, int n_in,
                              void* d_out, int out_size) {
    // metadata order: keypoints, std_x, std_y, correlation, DetectionMap (unused)
    const float* kp   = (const float*)d_in[0];
    const float* psx  = (const float*)d_in[1];
    const float* psy  = (const float*)d_in[2];
    const float* prho = (const float*)d_in[3];
    float* out = (float*)d_out;

    const int total_threads = NWARPS * 32;            // 819200
    recon_conf_map_kernel<<<total_threads / NTHR, NTHR>>>(kp, psx, psy, prho, out);
}